// round 8
// baseline (speedup 1.0000x reference)
#include <cuda_runtime.h>

// ---------------------------------------------------------------------------
// LMMD loss, fused.
//   B=4096 rows each of source/target, D=256, 31 classes, 5 RBF kernels.
//
// Structure:
//   bw computed in closed form:  sum(l2) = 2n*sum(||x||^2) - 2*||sum x||^2
//   kernels(l2) = z + z^2 + z^4 + z^8 + z^16,  z = exp(-l2/(16*bw))  (1 MUFU)
//   loss = (1/n_idx) * sum_{p,q} (u_p . u_q) * K[p,q],
//     u_p = s_vec row (+) for source rows, -t_vec row for target rows.
//   Symmetric: only tile pairs I<=J computed (x2 off-diagonal).
// ---------------------------------------------------------------------------

#define B_ROWS 4096
#define D_DIM  256
#define NCLS   31
#define NTOT   8192            // 2B
#define BM     128             // tile size
#define BK     16              // k-chunk
#define NT     64              // NTOT / BM
#define NPAIR  2080            // NT*(NT+1)/2

// ---- device scratch (no allocations allowed) ----
__device__ float d_W[NTOT * 32];       // signed per-row class weights, padded to 32
__device__ float d_sq[NTOT];           // ||x_p||^2
__device__ float d_colsum[D_DIM];      // sum over rows per column
__device__ float d_scnt[NCLS];
__device__ float d_tcnt[NCLS];
__device__ float d_targc[NCLS];        // argmax presence counts
__device__ float d_sscale[NCLS];
__device__ float d_tscale[NCLS];
__device__ float d_cz;                 // -log2(e) / (16*bw)
__device__ float d_inv_nidx;
__device__ float d_partial[NPAIR];
__device__ int   d_lab64;              // 1 if labels are int64, 0 if int32

__device__ __forceinline__ const float* row_ptr(const float* s, const float* t, int p) {
    return (p < B_ROWS) ? (s + (size_t)p * D_DIM)
                        : (t + (size_t)(p - B_ROWS) * D_DIM);
}

__device__ __forceinline__ int get_label(const void* sl, int i) {
    if (d_lab64) return (int)((const long long*)sl)[i];
    return ((const int*)sl)[i];
}

// ---------------------------------------------------------------------------
// Detect label dtype: if int64 (little-endian), every odd int32 word (high
// half) over the first 2048 labels is 0. If int32, those words are random
// labels in [0,31) and are nonzero w.h.p. (P(all zero) ~ (1/31)^2048).
// Reads stay within 4096 int32s, safe under either true dtype.
// ---------------------------------------------------------------------------
__global__ void k_detect(const void* sl) {
    __shared__ int any;
    if (threadIdx.x == 0) any = 0;
    __syncthreads();
    const int* a = (const int*)sl;
    int local = 0;
    for (int i = threadIdx.x; i < 2048; i += blockDim.x)
        if (a[2 * i + 1] != 0) local = 1;
    if (local) atomicOr(&any, 1);
    __syncthreads();
    if (threadIdx.x == 0) d_lab64 = any ? 0 : 1;
}

__global__ void k_zero() {
    int t = threadIdx.x;
    if (t < NCLS) { d_scnt[t] = 0.f; d_tcnt[t] = 0.f; d_targc[t] = 0.f; }
    if (t < D_DIM) d_colsum[t] = 0.f;
}

// class statistics: s_cnt, t_cnt (column sums of t_label), argmax presence
__global__ void k_stats(const void* sl, const float* __restrict__ tl) {
    __shared__ float ssh[NCLS], tsh[NCLS], ash[NCLS];
    int tid = threadIdx.x;
    if (tid < NCLS) { ssh[tid] = 0.f; tsh[tid] = 0.f; ash[tid] = 0.f; }
    __syncthreads();

    int i = blockIdx.x * 256 + tid;          // grid 16 x 256 == B_ROWS
    int lab = get_label(sl, i);
    atomicAdd(&ssh[lab], 1.f);

    const float* row = tl + (size_t)i * NCLS;
    float best = row[0];
    int arg = 0;
    atomicAdd(&tsh[0], best);
    #pragma unroll
    for (int c = 1; c < NCLS; c++) {
        float v = row[c];
        atomicAdd(&tsh[c], v);
        if (v > best) { best = v; arg = c; }  // strict > == jnp first-max tie break
    }
    atomicAdd(&ash[arg], 1.f);
    __syncthreads();
    if (tid < NCLS) {
        atomicAdd(&d_scnt[tid],  ssh[tid]);
        atomicAdd(&d_tcnt[tid],  tsh[tid]);
        atomicAdd(&d_targc[tid], ash[tid]);
    }
}

// column sums over all 8192 rows (thread = column, coalesced)
__global__ void k_colsum(const float* __restrict__ src, const float* __restrict__ tgt) {
    int c = threadIdx.x;
    int r0 = blockIdx.x * 128;               // grid 64
    float acc = 0.f;
    for (int r = 0; r < 128; r++) {
        const float* p = row_ptr(src, tgt, r0 + r);
        acc += p[c];
    }
    atomicAdd(&d_colsum[c], acc);
}

// per-row squared norms: one warp per row
__global__ void k_sq(const float* __restrict__ src, const float* __restrict__ tgt) {
    int w = threadIdx.x >> 5, lane = threadIdx.x & 31;
    int row = blockIdx.x * 8 + w;            // grid 1024
    const float* p = row_ptr(src, tgt, row);
    float4 v0 = *(const float4*)(p + lane * 8);
    float4 v1 = *(const float4*)(p + lane * 8 + 4);
    float s = v0.x * v0.x + v0.y * v0.y + v0.z * v0.z + v0.w * v0.w
            + v1.x * v1.x + v1.y * v1.y + v1.z * v1.z + v1.w * v1.w;
    #pragma unroll
    for (int off = 16; off > 0; off >>= 1)
        s += __shfl_xor_sync(0xffffffffu, s, off);
    if (lane == 0) d_sq[row] = s;
}

// mask/scales/n_idx + bandwidth in closed form (double accumulation)
__global__ void k_finalize() {
    __shared__ double dred[256];
    int tid = threadIdx.x;

    if (tid == 0) {
        float nidx = 0.f;
        for (int c = 0; c < NCLS; c++) {
            float m = (d_scnt[c] > 0.f && d_targc[c] > 0.f) ? 1.f : 0.f;
            nidx += m;
            float sden = (d_scnt[c] == 0.f) ? 100.f : d_scnt[c];
            float tden = (d_tcnt[c] == 0.f) ? 100.f : d_tcnt[c];
            d_sscale[c] = m / sden;
            d_tscale[c] = m / tden;
        }
        if (nidx < 1.f) nidx = 1.f;
        d_inv_nidx = 1.f / nidx;
    }

    double s = 0.0;
    for (int i = tid; i < NTOT; i += 256)
        s += (double)d_sq[i] * (2.0 * (double)NTOT);
    for (int i = tid; i < D_DIM; i += 256) {
        double v = (double)d_colsum[i];
        s -= 2.0 * v * v;
    }
    dred[tid] = s;
    __syncthreads();
    for (int st = 128; st > 0; st >>= 1) {
        if (tid < st) dred[tid] += dred[tid + st];
        __syncthreads();
    }
    if (tid == 0) {
        double suml2 = dred[0];
        float bw = (float)(suml2 / (8192.0 * 8192.0 - 8192.0));
        bw = fmaxf(bw, 1e-6f) * 0.25f;      // / KERNEL_MUL^(KERNEL_NUM//2)
        // z = exp(-l2/(16 bw)) = exp2f(l2 * cz)
        d_cz = -1.4426950408889634f / (bw * 16.f);
    }
}

// build signed weight rows (padded to 32 floats)
__global__ void k_weights(const void* sl, const float* __restrict__ tl) {
    int p = blockIdx.x * 256 + threadIdx.x;  // grid 32 -> 8192
    float* w = d_W + (size_t)p * 32;
    if (p < B_ROWS) {
        int lab = get_label(sl, p);
        float v = d_sscale[lab];
        #pragma unroll
        for (int c = 0; c < 32; c++) w[c] = (c == lab) ? v : 0.f;
    } else {
        int i = p - B_ROWS;
        const float* row = tl + (size_t)i * NCLS;
        #pragma unroll
        for (int c = 0; c < NCLS; c++) w[c] = -row[c] * d_tscale[c];
        w[31] = 0.f;
    }
}

// ---------------------------------------------------------------------------
// Main fused tile kernel: 128x128 tile pairs (I<=J), K=256 fp32 GEMM,
// fused RBF-kernel + rank-31 weight epilogue, per-block partial sum.
// Thread tile 8x8: rows a = ty*8+i (contiguous), cols b = tx+16*j (strided,
// keeps all shared reads conflict-free incl. the weight epilogue).
// ---------------------------------------------------------------------------
__global__ __launch_bounds__(256, 2)
void k_main(const float* __restrict__ src, const float* __restrict__ tgt) {
    __shared__ union {
        struct { float A[BK][BM]; float Bt[BK][BM]; } m;   // 16 KB mainloop
        struct { float WA[BM * 32]; float WB[32 * BM]; } e; // 32 KB epilogue
        float red[256];
    } sm;

    // decode upper-triangular tile pair (I, J), I<=J
    int t = blockIdx.x;
    int I = 0;
    while ((I + 1) * NT - ((I + 1) * I) / 2 <= t) I++;
    int J = I + (t - (I * NT - (I * (I - 1)) / 2));
    int rowA = I * BM, rowB = J * BM;

    int tid  = threadIdx.x;
    int tx   = tid & 15, ty = tid >> 4;
    int lrow = tid >> 1, half = tid & 1;

    const float* pa = row_ptr(src, tgt, rowA + lrow);
    const float* pb = row_ptr(src, tgt, rowB + lrow);

    float acc[8][8];
    #pragma unroll
    for (int i = 0; i < 8; i++)
        #pragma unroll
        for (int j = 0; j < 8; j++) acc[i][j] = 0.f;

    for (int k0 = 0; k0 < D_DIM; k0 += BK) {
        // prefetch global before the sync (overlaps with previous compute)
        float4 a0 = *(const float4*)(pa + k0 + half * 8);
        float4 a1 = *(const float4*)(pa + k0 + half * 8 + 4);
        float4 b0 = *(const float4*)(pb + k0 + half * 8);
        float4 b1 = *(const float4*)(pb + k0 + half * 8 + 4);
        __syncthreads();
        int kb = half * 8;
        sm.m.A [kb + 0][lrow] = a0.x; sm.m.A [kb + 1][lrow] = a0.y;
        sm.m.A [kb + 2][lrow] = a0.z; sm.m.A [kb + 3][lrow] = a0.w;
        sm.m.A [kb + 4][lrow] = a1.x; sm.m.A [kb + 5][lrow] = a1.y;
        sm.m.A [kb + 6][lrow] = a1.z; sm.m.A [kb + 7][lrow] = a1.w;
        sm.m.Bt[kb + 0][lrow] = b0.x; sm.m.Bt[kb + 1][lrow] = b0.y;
        sm.m.Bt[kb + 2][lrow] = b0.z; sm.m.Bt[kb + 3][lrow] = b0.w;
        sm.m.Bt[kb + 4][lrow] = b1.x; sm.m.Bt[kb + 5][lrow] = b1.y;
        sm.m.Bt[kb + 6][lrow] = b1.z; sm.m.Bt[kb + 7][lrow] = b1.w;
        __syncthreads();

        #pragma unroll
        for (int k = 0; k < BK; k++) {
            float ar[8], br[8];
            float4 af0 = *(const float4*)&sm.m.A[k][ty * 8];
            float4 af1 = *(const float4*)&sm.m.A[k][ty * 8 + 4];
            ar[0] = af0.x; ar[1] = af0.y; ar[2] = af0.z; ar[3] = af0.w;
            ar[4] = af1.x; ar[5] = af1.y; ar[6] = af1.z; ar[7] = af1.w;
            #pragma unroll
            for (int j = 0; j < 8; j++) br[j] = sm.m.Bt[k][tx + 16 * j];
            #pragma unroll
            for (int i = 0; i < 8; i++)
                #pragma unroll
                for (int j = 0; j < 8; j++)
                    acc[i][j] = fmaf(ar[i], br[j], acc[i][j]);
        }
    }

    // ---- epilogue: stage weight tiles into shared (WB transposed) ----
    __syncthreads();
    {
        const float* wasrc = d_W + (size_t)rowA * 32;
        for (int m = tid * 4; m < BM * 32; m += 256 * 4)
            *(float4*)&sm.e.WA[m] = *(const float4*)&wasrc[m];
        const float* wbsrc = d_W + (size_t)rowB * 32;
        for (int g = tid; g < BM * 32; g += 256) {
            int b = g >> 5, c = g & 31;
            sm.e.WB[c * BM + b] = wbsrc[g];
        }
    }
    __syncthreads();

    float sqa[8], sqb[8];
    #pragma unroll
    for (int i = 0; i < 8; i++) sqa[i] = d_sq[rowA + ty * 8 + i];
    #pragma unroll
    for (int j = 0; j < 8; j++) sqb[j] = d_sq[rowB + tx + 16 * j];
    float cz = d_cz;

    // acc -> summed RBF kernel values: z + z^2 + z^4 + z^8 + z^16
    #pragma unroll
    for (int i = 0; i < 8; i++)
        #pragma unroll
        for (int j = 0; j < 8; j++) {
            float g  = acc[i][j];
            float l2 = fmaxf(sqa[i] + sqb[j] - 2.f * g, 0.f);
            float z  = exp2f(l2 * cz);
            float z2 = z * z, z4 = z2 * z2, z8 = z4 * z4, z16 = z8 * z8;
            acc[i][j] = ((z + z2) + (z4 + z8)) + z16;
        }

    // weighted reduction over 31 classes
    float lsum = 0.f;
    #pragma unroll
    for (int c = 0; c < NCLS; c++) {
        float wb[8];
        #pragma unroll
        for (int j = 0; j < 8; j++) wb[j] = sm.e.WB[c * BM + tx + 16 * j];
        #pragma unroll
        for (int i = 0; i < 8; i++) {
            float s = 0.f;
            #pragma unroll
            for (int j = 0; j < 8; j++) s = fmaf(wb[j], acc[i][j], s);
            float wa = sm.e.WA[(ty * 8 + i) * 32 + c];
            lsum = fmaf(wa, s, lsum);
        }
    }
    if (I != J) lsum *= 2.f;

    // block reduction (deterministic)
    __syncthreads();                  // protect WA/WB reads before aliasing red[]
    sm.red[tid] = lsum;
    __syncthreads();
    for (int st = 128; st > 0; st >>= 1) {
        if (tid < st) sm.red[tid] += sm.red[tid + st];
        __syncthreads();
    }
    if (tid == 0) d_partial[blockIdx.x] = sm.red[0];
}

__global__ void k_reduce(float* out) {
    __shared__ float red[256];
    int tid = threadIdx.x;
    float s = 0.f;
    for (int i = tid; i < NPAIR; i += 256) s += d_partial[i];
    red[tid] = s;
    __syncthreads();
    for (int st = 128; st > 0; st >>= 1) {
        if (tid < st) red[tid] += red[tid + st];
        __syncthreads();
    }
    if (tid == 0) out[0] = red[0] * d_inv_nidx;
}

extern "C" void kernel_launch(void* const* d_in, const int* in_sizes, int n_in,
                              void* d_out, int out_size) {
    const float* src = (const float*)d_in[0];
    const float* tgt = (const float*)d_in[1];
    const void*  sl  = d_in[2];
    const float* tl  = (const float*)d_in[3];
    float* out = (float*)d_out;

    k_detect  <<<1,    256>>>(sl);
    k_zero    <<<1,    256>>>();
    k_stats   <<<16,   256>>>(sl, tl);
    k_colsum  <<<64,   256>>>(src, tgt);
    k_sq      <<<1024, 256>>>(src, tgt);
    k_finalize<<<1,    256>>>();
    k_weights <<<32,   256>>>(sl, tl);
    k_main    <<<NPAIR, 256>>>(src, tgt);
    k_reduce  <<<1,    256>>>(out);
}

// round 11
// speedup vs baseline: 1.6058x; 1.6058x over previous
#include <cuda_runtime.h>
#include <cuda_bf16.h>
#include <cstdint>

// ---------------------------------------------------------------------------
// LMMD loss — HMMA (mma.sync bf16, 3-term split) Gram mainloop + fused epilogue.
//   bw closed form: sum(l2) = 2n*sum(||x||^2) - 2*||sum x||^2
//   K(l2) = z + z^2 + z^4 + z^8 + z^16, z = exp(-l2/(16*bw))
//   loss = (1/n_idx) * sum_pq (u_p.u_q) K_pq, u = +s_vec / -t_vec rows.
//   Upper-triangular 128x128 tiles only (x2 off-diagonal).
//   g = A_hi*B_hi + A_hi*B_lo + A_lo*B_hi  (fp32 accum in registers)
// NOTE: tcgen05 is unusable (harness builds via compute_103 non-'a' PTX);
//       mma.sync.m16n8k16 is arch-generic sm_80+ PTX.
// ---------------------------------------------------------------------------

#define B_ROWS 4096
#define D_DIM  256
#define NCLS   31
#define NTOT   8192
#define BM     128
#define KC     64              // K per chunk = 128B bf16 rows (swizzle atom)
#define NCHUNK 4
#define NT     64
#define NPAIR  2080
#define NSRCT  32              // tiles 0..31 hold source rows

// ---- device scratch ----
__device__ __align__(16) __nv_bfloat16 d_Xhi[NTOT * D_DIM];
__device__ __align__(16) __nv_bfloat16 d_Xlo[NTOT * D_DIM];
__device__ __align__(16) float d_W[NTOT * 32];
__device__ int   d_labS[B_ROWS];
__device__ float d_sq[NTOT];
__device__ float d_colsum[D_DIM];
__device__ float d_scnt[NCLS];
__device__ float d_tcnt[NCLS];
__device__ float d_targc[NCLS];
__device__ float d_sscale[NCLS];
__device__ float d_tscale[NCLS];
__device__ float d_cz;
__device__ float d_inv_nidx;
__device__ float d_partial[NPAIR];
__device__ int   d_lab64;

// ---- helpers ----
__device__ __forceinline__ uint32_t smem_u32(const void* p) {
    uint32_t a;
    asm("{ .reg .u64 t; cvta.to.shared.u64 t, %1; cvt.u32.u64 %0, t; }" : "=r"(a) : "l"(p));
    return a;
}
#define CP_ASYNC16(dst, src) \
    asm volatile("cp.async.cg.shared.global [%0], [%1], 16;" :: "r"(dst), "l"(src))
#define CP_COMMIT() asm volatile("cp.async.commit_group;" ::: "memory")
#define CP_WAIT(n)  asm volatile("cp.async.wait_group %0;" :: "n"(n) : "memory")

#define LDSM4(r, a) \
    asm volatile("ldmatrix.sync.aligned.m8n8.x4.shared.b16 {%0,%1,%2,%3}, [%4];" \
        : "=r"((r)[0]), "=r"((r)[1]), "=r"((r)[2]), "=r"((r)[3]) : "r"(a))

__device__ __forceinline__ void mma_bf16(float* c, const uint32_t* a, const uint32_t* b) {
    asm volatile(
        "mma.sync.aligned.m16n8k16.row.col.f32.bf16.bf16.f32 "
        "{%0,%1,%2,%3}, {%4,%5,%6,%7}, {%8,%9}, {%0,%1,%2,%3};"
        : "+f"(c[0]), "+f"(c[1]), "+f"(c[2]), "+f"(c[3])
        : "r"(a[0]), "r"(a[1]), "r"(a[2]), "r"(a[3]), "r"(b[0]), "r"(b[1]));
}

__device__ __forceinline__ const float* row_ptr(const float* s, const float* t, int p) {
    return (p < B_ROWS) ? (s + (size_t)p * D_DIM) : (t + (size_t)(p - B_ROWS) * D_DIM);
}
__device__ __forceinline__ int get_label(const void* sl, int i) {
    if (d_lab64) return (int)((const long long*)sl)[i];
    return ((const int*)sl)[i];
}

// ---------------------------------------------------------------------------
// small kernels
// ---------------------------------------------------------------------------
__global__ void k_detect(const void* sl) {
    __shared__ int any;
    if (threadIdx.x == 0) any = 0;
    __syncthreads();
    const int* a = (const int*)sl;
    int local = 0;
    for (int i = threadIdx.x; i < 2048; i += blockDim.x)
        if (a[2 * i + 1] != 0) local = 1;
    if (local) atomicOr(&any, 1);
    __syncthreads();
    if (threadIdx.x == 0) d_lab64 = any ? 0 : 1;
}

__global__ void k_zero() {
    int t = threadIdx.x;
    if (t < NCLS) { d_scnt[t] = 0.f; d_tcnt[t] = 0.f; d_targc[t] = 0.f; }
    if (t < D_DIM) d_colsum[t] = 0.f;
}

__global__ void k_stats(const void* sl, const float* __restrict__ tl) {
    __shared__ float ssh[NCLS], tsh[NCLS], ash[NCLS];
    int tid = threadIdx.x;
    if (tid < NCLS) { ssh[tid] = 0.f; tsh[tid] = 0.f; ash[tid] = 0.f; }
    __syncthreads();
    int i = blockIdx.x * 256 + tid;
    int lab = get_label(sl, i);
    atomicAdd(&ssh[lab], 1.f);
    const float* row = tl + (size_t)i * NCLS;
    float best = row[0];
    int arg = 0;
    atomicAdd(&tsh[0], best);
    #pragma unroll
    for (int c = 1; c < NCLS; c++) {
        float v = row[c];
        atomicAdd(&tsh[c], v);
        if (v > best) { best = v; arg = c; }
    }
    atomicAdd(&ash[arg], 1.f);
    __syncthreads();
    if (tid < NCLS) {
        atomicAdd(&d_scnt[tid],  ssh[tid]);
        atomicAdd(&d_tcnt[tid],  tsh[tid]);
        atomicAdd(&d_targc[tid], ash[tid]);
    }
}

// fused: column sums + row sq-norms + bf16 hi/lo split.  grid 1024 x 256
__global__ void k_prep(const float* __restrict__ src, const float* __restrict__ tgt) {
    __shared__ float cs[256];
    int tid = threadIdx.x;
    cs[tid] = 0.f;
    __syncthreads();
    int w = tid >> 5, lane = tid & 31;
    int row = blockIdx.x * 8 + w;
    const float* p = row_ptr(src, tgt, row) + lane * 8;
    float4 v0 = *(const float4*)p;
    float4 v1 = *(const float4*)(p + 4);
    float xs[8] = {v0.x, v0.y, v0.z, v0.w, v1.x, v1.y, v1.z, v1.w};

    float s = 0.f;
    #pragma unroll
    for (int e = 0; e < 8; e++) s = fmaf(xs[e], xs[e], s);
    #pragma unroll
    for (int off = 16; off > 0; off >>= 1) s += __shfl_xor_sync(0xffffffffu, s, off);
    if (lane == 0) d_sq[row] = s;

    int cb = lane * 8;
    #pragma unroll
    for (int e = 0; e < 8; e++) atomicAdd(&cs[cb + e], xs[e]);

    uint32_t ph[4], pl[4];
    #pragma unroll
    for (int e = 0; e < 4; e++) {
        __nv_bfloat16 h0 = __float2bfloat16_rn(xs[2 * e]);
        __nv_bfloat16 h1 = __float2bfloat16_rn(xs[2 * e + 1]);
        __nv_bfloat16 l0 = __float2bfloat16_rn(xs[2 * e]     - __bfloat162float(h0));
        __nv_bfloat16 l1 = __float2bfloat16_rn(xs[2 * e + 1] - __bfloat162float(h1));
        ph[e] = (uint32_t)__bfloat16_as_ushort(h0) | ((uint32_t)__bfloat16_as_ushort(h1) << 16);
        pl[e] = (uint32_t)__bfloat16_as_ushort(l0) | ((uint32_t)__bfloat16_as_ushort(l1) << 16);
    }
    size_t o = (size_t)row * D_DIM + lane * 8;
    *(uint4*)(d_Xhi + o) = make_uint4(ph[0], ph[1], ph[2], ph[3]);
    *(uint4*)(d_Xlo + o) = make_uint4(pl[0], pl[1], pl[2], pl[3]);

    __syncthreads();
    atomicAdd(&d_colsum[tid], cs[tid]);
}

__global__ void k_finalize() {
    __shared__ double dred[256];
    int tid = threadIdx.x;
    if (tid == 0) {
        float nidx = 0.f;
        for (int c = 0; c < NCLS; c++) {
            float m = (d_scnt[c] > 0.f && d_targc[c] > 0.f) ? 1.f : 0.f;
            nidx += m;
            float sden = (d_scnt[c] == 0.f) ? 100.f : d_scnt[c];
            float tden = (d_tcnt[c] == 0.f) ? 100.f : d_tcnt[c];
            d_sscale[c] = m / sden;
            d_tscale[c] = m / tden;
        }
        if (nidx < 1.f) nidx = 1.f;
        d_inv_nidx = 1.f / nidx;
    }
    double s = 0.0;
    for (int i = tid; i < NTOT; i += 256)
        s += (double)d_sq[i] * (2.0 * (double)NTOT);
    for (int i = tid; i < D_DIM; i += 256) {
        double v = (double)d_colsum[i];
        s -= 2.0 * v * v;
    }
    dred[tid] = s;
    __syncthreads();
    for (int st = 128; st > 0; st >>= 1) {
        if (tid < st) dred[tid] += dred[tid + st];
        __syncthreads();
    }
    if (tid == 0) {
        float bw = (float)(dred[0] / (8192.0 * 8192.0 - 8192.0));
        bw = fmaxf(bw, 1e-6f) * 0.25f;
        d_cz = -1.4426950408889634f / (bw * 16.f);
    }
}

__global__ void k_weights(const void* sl, const float* __restrict__ tl) {
    int p = blockIdx.x * 256 + threadIdx.x;
    float* w = d_W + (size_t)p * 32;
    if (p < B_ROWS) {
        int lab = get_label(sl, p);
        d_labS[p] = lab;
        float v = d_sscale[lab];
        #pragma unroll
        for (int c = 0; c < 32; c++) w[c] = (c == lab) ? v : 0.f;
    } else {
        int i = p - B_ROWS;
        const float* row = tl + (size_t)i * NCLS;
        #pragma unroll
        for (int c = 0; c < NCLS; c++) w[c] = -row[c] * d_tscale[c];
        w[31] = 0.f;
    }
}

// ---------------------------------------------------------------------------
// main tile kernel.
// Dynamic SMEM 131072 B: 2 buffers x {Ahi,Alo,Bhi,Blo} x (128 rows x 128 B).
// Swizzle: 16B chunk index c (0..7) within a 128B row stored at c ^ (row&7).
// Epilogue overlays buffer 0.
// ---------------------------------------------------------------------------
#define SM_TOTAL 131072
#define EP_SQA  0
#define EP_SQB  512
#define EP_LABA 1024
#define EP_LABB 1536
#define EP_SVA  2048
#define EP_SVB  2560
#define EP_WA   3072      // [128][32] f32, 16 KB
#define EP_WBT  19456     // [32][132] f32, 16.9 KB
#define EP_RED  36352

__global__ __launch_bounds__(256, 1)
void k_main() {
    extern __shared__ char smem[];
    uint32_t sb = smem_u32(smem);
    int tid = threadIdx.x, wid = tid >> 5, lane = tid & 31;
    int g = lane >> 2, t4 = lane & 3;
    int warp_m = wid & 3, warp_n = wid >> 2;

    // decode upper-triangular tile pair (I <= J)
    int t = blockIdx.x;
    int I = 0;
    while ((I + 1) * NT - ((I + 1) * I) / 2 <= t) I++;
    int J = I + (t - (I * NT - (I * (I - 1)) / 2));
    int rowA = I * BM, rowB = J * BM;

    // ldmatrix per-lane row mapping (x4: mats 0..3 from lane groups of 8)
    int a_rl  = (lane & 7) + ((lane >> 3) & 1) * 8;   // A local row 0..15
    int a_blk = lane >> 4;                            // A k-16B-block 0/1
    int b_nl  = (lane & 7) + ((lane >> 4) << 3);      // B local n 0..15
    int b_blk = (lane >> 3) & 1;

    uint32_t arow_off[2], ar7[2];
    #pragma unroll
    for (int mt = 0; mt < 2; mt++) {
        int r = warp_m * 32 + mt * 16 + a_rl;
        arow_off[mt] = (uint32_t)r * 128;
        ar7[mt] = (uint32_t)(r & 7);
    }
    uint32_t brow_off[4], br7[4];
    #pragma unroll
    for (int ng = 0; ng < 4; ng++) {
        int r = warp_n * 64 + ng * 16 + b_nl;
        brow_off[ng] = (uint32_t)r * 128;
        br7[ng] = (uint32_t)(r & 7);
    }

    float acc[2][8][4];
    #pragma unroll
    for (int mt = 0; mt < 2; mt++)
        #pragma unroll
        for (int nt = 0; nt < 8; nt++)
            #pragma unroll
            for (int e = 0; e < 4; e++) acc[mt][nt][e] = 0.f;

    // --- cp.async chunk loader: 16 x 16B per thread per chunk ---
    auto issue = [&](int ch, int buf) {
        int k0 = ch * KC;
        #pragma unroll
        for (int i = 0; i < 16; i++) {
            int q = i * 256 + tid;
            int tile = q >> 10;           // 0:Ahi 1:Alo 2:Bhi 3:Blo
            int idx = q & 1023;
            int row = idx >> 3;
            int c   = idx & 7;
            const __nv_bfloat16* X = (tile == 0 || tile == 2) ? d_Xhi : d_Xlo;
            int rb = (tile < 2) ? rowA : rowB;
            const __nv_bfloat16* src = X + (size_t)(rb + row) * D_DIM + k0 + c * 8;
            uint32_t dst = sb + (uint32_t)buf * 65536 + (uint32_t)tile * 16384
                         + (uint32_t)row * 128 + (uint32_t)((c ^ (row & 7)) << 4);
            CP_ASYNC16(dst, src);
        }
        CP_COMMIT();
    };

    issue(0, 0);
    for (int ch = 0; ch < NCHUNK; ch++) {
        int buf = ch & 1;
        if (ch < NCHUNK - 1) issue(ch + 1, (ch + 1) & 1);
        if (ch < NCHUNK - 1) CP_WAIT(1); else CP_WAIT(0);
        __syncthreads();

        uint32_t bufb = sb + (uint32_t)buf * 65536;
        #pragma unroll
        for (int ks = 0; ks < 4; ks++) {
            uint32_t ah[2][4], al[2][4], bb[4][4];
            #pragma unroll
            for (int mt = 0; mt < 2; mt++) {
                uint32_t ca = (((uint32_t)(ks * 2 + a_blk)) ^ ar7[mt]) << 4;
                LDSM4(ah[mt], bufb + arow_off[mt] + ca);
                LDSM4(al[mt], bufb + 16384 + arow_off[mt] + ca);
            }
            uint32_t cb[4];
            #pragma unroll
            for (int ng = 0; ng < 4; ng++) {
                cb[ng] = (((uint32_t)(ks * 2 + b_blk)) ^ br7[ng]) << 4;
                LDSM4(bb[ng], bufb + 32768 + brow_off[ng] + cb[ng]);
            }
            // hi*hi and lo*hi
            #pragma unroll
            for (int mt = 0; mt < 2; mt++)
                #pragma unroll
                for (int nt = 0; nt < 8; nt++)
                    mma_bf16(acc[mt][nt], ah[mt], &bb[nt >> 1][(nt & 1) * 2]);
            #pragma unroll
            for (int mt = 0; mt < 2; mt++)
                #pragma unroll
                for (int nt = 0; nt < 8; nt++)
                    mma_bf16(acc[mt][nt], al[mt], &bb[nt >> 1][(nt & 1) * 2]);
            // hi*lo
            #pragma unroll
            for (int ng = 0; ng < 4; ng++)
                LDSM4(bb[ng], bufb + 49152 + brow_off[ng] + cb[ng]);
            #pragma unroll
            for (int mt = 0; mt < 2; mt++)
                #pragma unroll
                for (int nt = 0; nt < 8; nt++)
                    mma_bf16(acc[mt][nt], ah[mt], &bb[nt >> 1][(nt & 1) * 2]);
        }
        __syncthreads();
    }

    // ---- stage epilogue operands (overlays buffer region; loads drained) ----
    bool srcA = (I < NSRCT), srcB = (J < NSRCT);
    float* SQA  = (float*)(smem + EP_SQA);
    float* SQB  = (float*)(smem + EP_SQB);
    int*   LABA = (int*)  (smem + EP_LABA);
    int*   LABB = (int*)  (smem + EP_LABB);
    float* SVA  = (float*)(smem + EP_SVA);
    float* SVB  = (float*)(smem + EP_SVB);
    float* WA   = (float*)(smem + EP_WA);
    float* WBT  = (float*)(smem + EP_WBT);
    float* RED  = (float*)(smem + EP_RED);

    if (tid < 128) { SQA[tid] = d_sq[rowA + tid]; SQB[tid] = d_sq[rowB + tid]; }
    if (srcA) {
        if (tid < 128) {
            int l = d_labS[rowA + tid];
            LABA[tid] = l; SVA[tid] = d_sscale[l];
        }
    } else {
        for (int m = tid * 4; m < BM * 32; m += 1024)
            *(float4*)&WA[m] = *(const float4*)&d_W[(size_t)rowA * 32 + m];
    }
    if (srcB) {
        if (tid < 128) {
            int l = d_labS[rowB + tid];
            LABB[tid] = l; SVB[tid] = d_sscale[l];
        }
    } else {
        for (int gq = tid; gq < BM * 32; gq += 256) {
            int j = gq >> 5, cc = gq & 31;
            WBT[cc * 132 + j] = d_W[(size_t)(rowB + j) * 32 + cc];
        }
    }
    __syncthreads();

    // ---- exp chain ----
    int rl[4], cl[16];
    float sqa4[4], sqb16[16];
    #pragma unroll
    for (int mt = 0; mt < 2; mt++)
        #pragma unroll
        for (int h = 0; h < 2; h++) {
            int r = warp_m * 32 + mt * 16 + h * 8 + g;
            rl[mt * 2 + h] = r; sqa4[mt * 2 + h] = SQA[r];
        }
    #pragma unroll
    for (int nt = 0; nt < 8; nt++)
        #pragma unroll
        for (int w = 0; w < 2; w++) {
            int c = warp_n * 64 + nt * 8 + 2 * t4 + w;
            cl[nt * 2 + w] = c; sqb16[nt * 2 + w] = SQB[c];
        }
    float cz = d_cz;
    float Kr[4][16];
    #pragma unroll
    for (int mt = 0; mt < 2; mt++)
        #pragma unroll
        for (int nt = 0; nt < 8; nt++)
            #pragma unroll
            for (int e = 0; e < 4; e++) {
                int r = mt * 2 + (e >> 1), c = nt * 2 + (e & 1);
                float l2 = fmaxf(sqa4[r] + sqb16[c] - 2.f * acc[mt][nt][e], 0.f);
                float z  = exp2f(l2 * cz);
                float z2 = z * z, z4 = z2 * z2, z8 = z4 * z4, z16 = z8 * z8;
                Kr[r][c] = ((z + z2) + (z4 + z8)) + z16;
            }

    // ---- weight contraction ----
    float lsum = 0.f;
    if (srcA) {
        int la[4]; float sa[4];
        #pragma unroll
        for (int r = 0; r < 4; r++) { la[r] = LABA[rl[r]]; sa[r] = SVA[rl[r]]; }
        if (srcB) {
            int lb[16]; float svb[16];
            #pragma unroll
            for (int j = 0; j < 16; j++) { lb[j] = LABB[cl[j]]; svb[j] = SVB[cl[j]]; }
            #pragma unroll
            for (int r = 0; r < 4; r++) {
                float s = 0.f;
                #pragma unroll
                for (int j = 0; j < 16; j++) {
                    float w = (lb[j] == la[r]) ? svb[j] : 0.f;
                    s = fmaf(w, Kr[r][j], s);
                }
                lsum = fmaf(sa[r], s, lsum);
            }
        } else {
            #pragma unroll
            for (int r = 0; r < 4; r++) {
                const float* wr = &WBT[la[r] * 132];
                float s = 0.f;
                #pragma unroll
                for (int j = 0; j < 16; j++)
                    s = fmaf(wr[cl[j]], Kr[r][j], s);
                lsum = fmaf(sa[r], s, lsum);
            }
        }
    } else {            // tt: both target
        for (int c = 0; c < NCLS; c++) {
            float wbv[16];
            #pragma unroll
            for (int j = 0; j < 16; j++) wbv[j] = WBT[c * 132 + cl[j]];
            #pragma unroll
            for (int r = 0; r < 4; r++) {
                float s = 0.f;
                #pragma unroll
                for (int j = 0; j < 16; j++) s = fmaf(wbv[j], Kr[r][j], s);
                lsum = fmaf(WA[rl[r] * 32 + c], s, lsum);
            }
        }
    }
    if (I != J) lsum *= 2.f;

    // ---- block reduction ----
    __syncthreads();
    RED[tid] = lsum;
    __syncthreads();
    for (int st = 128; st > 0; st >>= 1) {
        if (tid < st) RED[tid] += RED[tid + st];
        __syncthreads();
    }
    if (tid == 0) d_partial[blockIdx.x] = RED[0];
}

__global__ void k_reduce(float* out) {
    __shared__ float red[256];
    int tid = threadIdx.x;
    float s = 0.f;
    for (int i = tid; i < NPAIR; i += 256) s += d_partial[i];
    red[tid] = s;
    __syncthreads();
    for (int st = 128; st > 0; st >>= 1) {
        if (tid < st) red[tid] += red[tid + st];
        __syncthreads();
    }
    if (tid == 0) out[0] = red[0] * d_inv_nidx;
}

extern "C" void kernel_launch(void* const* d_in, const int* in_sizes, int n_in,
                              void* d_out, int out_size) {
    const float* src = (const float*)d_in[0];
    const float* tgt = (const float*)d_in[1];
    const void*  sl  = d_in[2];
    const float* tl  = (const float*)d_in[3];
    float* out = (float*)d_out;

    cudaFuncSetAttribute(k_main, cudaFuncAttributeMaxDynamicSharedMemorySize, SM_TOTAL);

    k_detect  <<<1,    256>>>(sl);
    k_zero    <<<1,    256>>>();
    k_stats   <<<16,   256>>>(sl, tl);
    k_prep    <<<1024, 256>>>(src, tgt);
    k_finalize<<<1,    256>>>();
    k_weights <<<32,   256>>>(sl, tl);
    k_main    <<<NPAIR, 256, SM_TOTAL>>>();
    k_reduce  <<<1,    256>>>(out);
}

// round 13
// speedup vs baseline: 1.8101x; 1.1272x over previous
#include <cuda_runtime.h>
#include <cuda_bf16.h>
#include <cstdint>

// ---------------------------------------------------------------------------
// LMMD loss — HMMA (mma.sync bf16, 3-term split) Gram mainloop + fused epilogue.
//   bw closed form: sum(l2) = 2n*sum(||x||^2) - 2*||sum x||^2
//   K(l2) = z + z^2 + z^4 + z^8 + z^16, z = exp(-l2/(16*bw))
//   loss = (1/n_idx) * sum_pq (u_p.u_q) K_pq, u = +s_vec / -t_vec rows.
//   Upper-triangular 128x128 tiles only (x2 off-diagonal).
//   g = A_hi*B_hi + A_hi*B_lo + A_lo*B_hi  (fp32 accum in registers)
// R12: KC=32, 3-stage cp.async pipeline, 96KB SMEM -> 2 CTAs/SM (was 1).
// ---------------------------------------------------------------------------

#define B_ROWS 4096
#define D_DIM  256
#define NCLS   31
#define NTOT   8192
#define BM     128
#define KC     32              // K per chunk = 64B bf16 rows
#define NCHUNK 8
#define NSTAGE 3
#define NT     64
#define NPAIR  2080
#define NSRCT  32              // tiles 0..31 hold source rows

#define STAGE_BYTES 32768      // 4 tiles x 128 rows x 64 B
#define TILE_BYTES  8192

// ---- device scratch ----
__device__ __align__(16) __nv_bfloat16 d_Xhi[NTOT * D_DIM];
__device__ __align__(16) __nv_bfloat16 d_Xlo[NTOT * D_DIM];
__device__ __align__(16) float d_W[NTOT * 32];
__device__ int   d_labS[B_ROWS];
__device__ float d_sq[NTOT];
__device__ float d_colsum[D_DIM];
__device__ float d_scnt[NCLS];
__device__ float d_tcnt[NCLS];
__device__ float d_targc[NCLS];
__device__ float d_sscale[NCLS];
__device__ float d_tscale[NCLS];
__device__ float d_cz;
__device__ float d_inv_nidx;
__device__ float d_partial[NPAIR];
__device__ int   d_lab64;

// ---- helpers ----
__device__ __forceinline__ uint32_t smem_u32(const void* p) {
    uint32_t a;
    asm("{ .reg .u64 t; cvta.to.shared.u64 t, %1; cvt.u32.u64 %0, t; }" : "=r"(a) : "l"(p));
    return a;
}
#define CP_ASYNC16(dst, src) \
    asm volatile("cp.async.cg.shared.global [%0], [%1], 16;" :: "r"(dst), "l"(src))
#define CP_COMMIT() asm volatile("cp.async.commit_group;" ::: "memory")
#define CP_WAIT(n)  asm volatile("cp.async.wait_group %0;" :: "n"(n) : "memory")

#define LDSM4(r, a) \
    asm volatile("ldmatrix.sync.aligned.m8n8.x4.shared.b16 {%0,%1,%2,%3}, [%4];" \
        : "=r"((r)[0]), "=r"((r)[1]), "=r"((r)[2]), "=r"((r)[3]) : "r"(a))

__device__ __forceinline__ void mma_bf16(float* c, const uint32_t* a, const uint32_t* b) {
    asm volatile(
        "mma.sync.aligned.m16n8k16.row.col.f32.bf16.bf16.f32 "
        "{%0,%1,%2,%3}, {%4,%5,%6,%7}, {%8,%9}, {%0,%1,%2,%3};"
        : "+f"(c[0]), "+f"(c[1]), "+f"(c[2]), "+f"(c[3])
        : "r"(a[0]), "r"(a[1]), "r"(a[2]), "r"(a[3]), "r"(b[0]), "r"(b[1]));
}

__device__ __forceinline__ const float* row_ptr(const float* s, const float* t, int p) {
    return (p < B_ROWS) ? (s + (size_t)p * D_DIM) : (t + (size_t)(p - B_ROWS) * D_DIM);
}
__device__ __forceinline__ int get_label(const void* sl, int i) {
    if (d_lab64) return (int)((const long long*)sl)[i];
    return ((const int*)sl)[i];
}

// ---------------------------------------------------------------------------
// small kernels
// ---------------------------------------------------------------------------
__global__ void k_detect(const void* sl) {
    __shared__ int any;
    if (threadIdx.x == 0) any = 0;
    __syncthreads();
    const int* a = (const int*)sl;
    int local = 0;
    for (int i = threadIdx.x; i < 2048; i += blockDim.x)
        if (a[2 * i + 1] != 0) local = 1;
    if (local) atomicOr(&any, 1);
    __syncthreads();
    if (threadIdx.x == 0) d_lab64 = any ? 0 : 1;
}

__global__ void k_zero() {
    int t = threadIdx.x;
    if (t < NCLS) { d_scnt[t] = 0.f; d_tcnt[t] = 0.f; d_targc[t] = 0.f; }
    if (t < D_DIM) d_colsum[t] = 0.f;
}

__global__ void k_stats(const void* sl, const float* __restrict__ tl) {
    __shared__ float ssh[NCLS], tsh[NCLS], ash[NCLS];
    int tid = threadIdx.x;
    if (tid < NCLS) { ssh[tid] = 0.f; tsh[tid] = 0.f; ash[tid] = 0.f; }
    __syncthreads();
    int i = blockIdx.x * 256 + tid;
    int lab = get_label(sl, i);
    atomicAdd(&ssh[lab], 1.f);
    const float* row = tl + (size_t)i * NCLS;
    float best = row[0];
    int arg = 0;
    atomicAdd(&tsh[0], best);
    #pragma unroll
    for (int c = 1; c < NCLS; c++) {
        float v = row[c];
        atomicAdd(&tsh[c], v);
        if (v > best) { best = v; arg = c; }
    }
    atomicAdd(&ash[arg], 1.f);
    __syncthreads();
    if (tid < NCLS) {
        atomicAdd(&d_scnt[tid],  ssh[tid]);
        atomicAdd(&d_tcnt[tid],  tsh[tid]);
        atomicAdd(&d_targc[tid], ash[tid]);
    }
}

// fused: column sums + row sq-norms + bf16 hi/lo split.  grid 1024 x 256
__global__ void k_prep(const float* __restrict__ src, const float* __restrict__ tgt) {
    __shared__ float cs[256];
    int tid = threadIdx.x;
    cs[tid] = 0.f;
    __syncthreads();
    int w = tid >> 5, lane = tid & 31;
    int row = blockIdx.x * 8 + w;
    const float* p = row_ptr(src, tgt, row) + lane * 8;
    float4 v0 = *(const float4*)p;
    float4 v1 = *(const float4*)(p + 4);
    float xs[8] = {v0.x, v0.y, v0.z, v0.w, v1.x, v1.y, v1.z, v1.w};

    float s = 0.f;
    #pragma unroll
    for (int e = 0; e < 8; e++) s = fmaf(xs[e], xs[e], s);
    #pragma unroll
    for (int off = 16; off > 0; off >>= 1) s += __shfl_xor_sync(0xffffffffu, s, off);
    if (lane == 0) d_sq[row] = s;

    int cb = lane * 8;
    #pragma unroll
    for (int e = 0; e < 8; e++) atomicAdd(&cs[cb + e], xs[e]);

    uint32_t ph[4], pl[4];
    #pragma unroll
    for (int e = 0; e < 4; e++) {
        __nv_bfloat16 h0 = __float2bfloat16_rn(xs[2 * e]);
        __nv_bfloat16 h1 = __float2bfloat16_rn(xs[2 * e + 1]);
        __nv_bfloat16 l0 = __float2bfloat16_rn(xs[2 * e]     - __bfloat162float(h0));
        __nv_bfloat16 l1 = __float2bfloat16_rn(xs[2 * e + 1] - __bfloat162float(h1));
        ph[e] = (uint32_t)__bfloat16_as_ushort(h0) | ((uint32_t)__bfloat16_as_ushort(h1) << 16);
        pl[e] = (uint32_t)__bfloat16_as_ushort(l0) | ((uint32_t)__bfloat16_as_ushort(l1) << 16);
    }
    size_t o = (size_t)row * D_DIM + lane * 8;
    *(uint4*)(d_Xhi + o) = make_uint4(ph[0], ph[1], ph[2], ph[3]);
    *(uint4*)(d_Xlo + o) = make_uint4(pl[0], pl[1], pl[2], pl[3]);

    __syncthreads();
    atomicAdd(&d_colsum[tid], cs[tid]);
}

__global__ void k_finalize() {
    __shared__ double dred[256];
    int tid = threadIdx.x;
    if (tid == 0) {
        float nidx = 0.f;
        for (int c = 0; c < NCLS; c++) {
            float m = (d_scnt[c] > 0.f && d_targc[c] > 0.f) ? 1.f : 0.f;
            nidx += m;
            float sden = (d_scnt[c] == 0.f) ? 100.f : d_scnt[c];
            float tden = (d_tcnt[c] == 0.f) ? 100.f : d_tcnt[c];
            d_sscale[c] = m / sden;
            d_tscale[c] = m / tden;
        }
        if (nidx < 1.f) nidx = 1.f;
        d_inv_nidx = 1.f / nidx;
    }
    double s = 0.0;
    for (int i = tid; i < NTOT; i += 256)
        s += (double)d_sq[i] * (2.0 * (double)NTOT);
    for (int i = tid; i < D_DIM; i += 256) {
        double v = (double)d_colsum[i];
        s -= 2.0 * v * v;
    }
    dred[tid] = s;
    __syncthreads();
    for (int st = 128; st > 0; st >>= 1) {
        if (tid < st) dred[tid] += dred[tid + st];
        __syncthreads();
    }
    if (tid == 0) {
        float bw = (float)(dred[0] / (8192.0 * 8192.0 - 8192.0));
        bw = fmaxf(bw, 1e-6f) * 0.25f;
        d_cz = -1.4426950408889634f / (bw * 16.f);
    }
}

__global__ void k_weights(const void* sl, const float* __restrict__ tl) {
    int p = blockIdx.x * 256 + threadIdx.x;
    float* w = d_W + (size_t)p * 32;
    if (p < B_ROWS) {
        int lab = get_label(sl, p);
        d_labS[p] = lab;
        float v = d_sscale[lab];
        #pragma unroll
        for (int c = 0; c < 32; c++) w[c] = (c == lab) ? v : 0.f;
    } else {
        int i = p - B_ROWS;
        const float* row = tl + (size_t)i * NCLS;
        #pragma unroll
        for (int c = 0; c < NCLS; c++) w[c] = -row[c] * d_tscale[c];
        w[31] = 0.f;
    }
}

// ---------------------------------------------------------------------------
// main tile kernel.
// Dynamic SMEM 98304 B: 3 stages x {Ahi,Alo,Bhi,Blo} x (128 rows x 64 B).
// Swizzle within 64B row: 16B chunk c (0..3) stored at c ^ ((row>>1)&3).
//   (conflict-free for ldmatrix: each parity group permutes its 4 slots,
//    parity groups land in disjoint 64B halves of the 128B bank window)
// Epilogue overlays stages 0-1 after all cp.async groups drained.
// ---------------------------------------------------------------------------
#define SM_TOTAL (NSTAGE * STAGE_BYTES)
#define EP_SQA  0
#define EP_SQB  512
#define EP_LABA 1024
#define EP_LABB 1536
#define EP_SVA  2048
#define EP_SVB  2560
#define EP_WA   3072      // [128][32] f32, 16 KB
#define EP_WBT  19456     // [32][132] f32, 16.9 KB
#define EP_RED  36352

__global__ __launch_bounds__(256, 2)
void k_main() {
    extern __shared__ char smem[];
    uint32_t sb = smem_u32(smem);
    int tid = threadIdx.x, wid = tid >> 5, lane = tid & 31;
    int g = lane >> 2, t4 = lane & 3;
    int warp_m = wid & 3, warp_n = wid >> 2;

    // decode upper-triangular tile pair (I <= J)
    int t = blockIdx.x;
    int I = 0;
    while ((I + 1) * NT - ((I + 1) * I) / 2 <= t) I++;
    int J = I + (t - (I * NT - (I * (I - 1)) / 2));
    int rowA = I * BM, rowB = J * BM;

    // ldmatrix per-lane row mapping (x4: mats 0..3 from lane groups of 8)
    int a_rl  = (lane & 7) + ((lane >> 3) & 1) * 8;   // A local row 0..15
    int a_blk = lane >> 4;                            // A k-16B-block 0/1
    int b_nl  = (lane & 7) + ((lane >> 4) << 3);      // B local n 0..15
    int b_blk = (lane >> 3) & 1;

    uint32_t arow_off[2], arsw[2];
    #pragma unroll
    for (int mt = 0; mt < 2; mt++) {
        int r = warp_m * 32 + mt * 16 + a_rl;
        arow_off[mt] = (uint32_t)r * 64;
        arsw[mt] = (uint32_t)((r >> 1) & 3);
    }
    uint32_t brow_off[4], brsw[4];
    #pragma unroll
    for (int ng = 0; ng < 4; ng++) {
        int r = warp_n * 64 + ng * 16 + b_nl;
        brow_off[ng] = (uint32_t)r * 64;
        brsw[ng] = (uint32_t)((r >> 1) & 3);
    }

    float acc[2][8][4];
    #pragma unroll
    for (int mt = 0; mt < 2; mt++)
        #pragma unroll
        for (int nt = 0; nt < 8; nt++)
            #pragma unroll
            for (int e = 0; e < 4; e++) acc[mt][nt][e] = 0.f;

    // --- cp.async chunk loader: 8 x 16B per thread per chunk (32 KB) ---
    auto issue = [&](int ch, int buf) {
        int k0 = ch * KC;
        #pragma unroll
        for (int i = 0; i < 8; i++) {
            int q = i * 256 + tid;
            int tile = q >> 9;            // 0:Ahi 1:Alo 2:Bhi 3:Blo (512 ops ea)
            int idx = q & 511;
            int row = idx >> 2;
            int c   = idx & 3;
            const __nv_bfloat16* X = (tile == 0 || tile == 2) ? d_Xhi : d_Xlo;
            int rb = (tile < 2) ? rowA : rowB;
            const __nv_bfloat16* src = X + (size_t)(rb + row) * D_DIM + k0 + c * 8;
            uint32_t dst = sb + (uint32_t)buf * STAGE_BYTES + (uint32_t)tile * TILE_BYTES
                         + (uint32_t)row * 64 + (uint32_t)((c ^ ((row >> 1) & 3)) << 4);
            CP_ASYNC16(dst, src);
        }
        CP_COMMIT();
    };

    issue(0, 0);
    issue(1, 1);
    for (int ch = 0; ch < NCHUNK; ch++) {
        int buf = ch % NSTAGE;
        if (ch + NSTAGE - 1 < NCHUNK) issue(ch + NSTAGE - 1, (ch + NSTAGE - 1) % NSTAGE);
        if (ch < NCHUNK - 2) CP_WAIT(2);
        else if (ch == NCHUNK - 2) CP_WAIT(1);
        else CP_WAIT(0);
        __syncthreads();

        uint32_t bufb = sb + (uint32_t)buf * STAGE_BYTES;
        #pragma unroll
        for (int ks = 0; ks < 2; ks++) {
            uint32_t ah[2][4], al[2][4], bb[4][4];
            #pragma unroll
            for (int mt = 0; mt < 2; mt++) {
                uint32_t ca = (((uint32_t)(ks * 2 + a_blk)) ^ arsw[mt]) << 4;
                LDSM4(ah[mt], bufb + arow_off[mt] + ca);
                LDSM4(al[mt], bufb + TILE_BYTES + arow_off[mt] + ca);
            }
            uint32_t cb[4];
            #pragma unroll
            for (int ng = 0; ng < 4; ng++) {
                cb[ng] = (((uint32_t)(ks * 2 + b_blk)) ^ brsw[ng]) << 4;
                LDSM4(bb[ng], bufb + 2 * TILE_BYTES + brow_off[ng] + cb[ng]);
            }
            // hi*hi and lo*hi
            #pragma unroll
            for (int mt = 0; mt < 2; mt++)
                #pragma unroll
                for (int nt = 0; nt < 8; nt++)
                    mma_bf16(acc[mt][nt], ah[mt], &bb[nt >> 1][(nt & 1) * 2]);
            #pragma unroll
            for (int mt = 0; mt < 2; mt++)
                #pragma unroll
                for (int nt = 0; nt < 8; nt++)
                    mma_bf16(acc[mt][nt], al[mt], &bb[nt >> 1][(nt & 1) * 2]);
            // hi*lo
            #pragma unroll
            for (int ng = 0; ng < 4; ng++)
                LDSM4(bb[ng], bufb + 3 * TILE_BYTES + brow_off[ng] + cb[ng]);
            #pragma unroll
            for (int mt = 0; mt < 2; mt++)
                #pragma unroll
                for (int nt = 0; nt < 8; nt++)
                    mma_bf16(acc[mt][nt], ah[mt], &bb[nt >> 1][(nt & 1) * 2]);
        }
        __syncthreads();
    }

    // ---- stage epilogue operands (overlays stages; all groups drained) ----
    bool srcA = (I < NSRCT), srcB = (J < NSRCT);
    float* SQA  = (float*)(smem + EP_SQA);
    float* SQB  = (float*)(smem + EP_SQB);
    int*   LABA = (int*)  (smem + EP_LABA);
    int*   LABB = (int*)  (smem + EP_LABB);
    float* SVA  = (float*)(smem + EP_SVA);
    float* SVB  = (float*)(smem + EP_SVB);
    float* WA   = (float*)(smem + EP_WA);
    float* WBT  = (float*)(smem + EP_WBT);
    float* RED  = (float*)(smem + EP_RED);

    if (tid < 128) { SQA[tid] = d_sq[rowA + tid]; SQB[tid] = d_sq[rowB + tid]; }
    if (srcA) {
        if (tid < 128) {
            int l = d_labS[rowA + tid];
            LABA[tid] = l; SVA[tid] = d_sscale[l];
        }
    } else {
        for (int m = tid * 4; m < BM * 32; m += 1024)
            *(float4*)&WA[m] = *(const float4*)&d_W[(size_t)rowA * 32 + m];
    }
    if (srcB) {
        if (tid < 128) {
            int l = d_labS[rowB + tid];
            LABB[tid] = l; SVB[tid] = d_sscale[l];
        }
    } else {
        for (int gq = tid; gq < BM * 32; gq += 256) {
            int j = gq >> 5, cc = gq & 31;
            WBT[cc * 132 + j] = d_W[(size_t)(rowB + j) * 32 + cc];
        }
    }
    __syncthreads();

    // ---- exp chain ----
    int rl[4], cl[16];
    float sqa4[4], sqb16[16];
    #pragma unroll
    for (int mt = 0; mt < 2; mt++)
        #pragma unroll
        for (int h = 0; h < 2; h++) {
            int r = warp_m * 32 + mt * 16 + h * 8 + g;
            rl[mt * 2 + h] = r; sqa4[mt * 2 + h] = SQA[r];
        }
    #pragma unroll
    for (int nt = 0; nt < 8; nt++)
        #pragma unroll
        for (int w = 0; w < 2; w++) {
            int c = warp_n * 64 + nt * 8 + 2 * t4 + w;
            cl[nt * 2 + w] = c; sqb16[nt * 2 + w] = SQB[c];
        }
    float cz = d_cz;
    float Kr[4][16];
    #pragma unroll
    for (int mt = 0; mt < 2; mt++)
        #pragma unroll
        for (int nt = 0; nt < 8; nt++)
            #pragma unroll
            for (int e = 0; e < 4; e++) {
                int r = mt * 2 + (e >> 1), c = nt * 2 + (e & 1);
                float l2 = fmaxf(sqa4[r] + sqb16[c] - 2.f * acc[mt][nt][e], 0.f);
                float z  = exp2f(l2 * cz);
                float z2 = z * z, z4 = z2 * z2, z8 = z4 * z4, z16 = z8 * z8;
                Kr[r][c] = ((z + z2) + (z4 + z8)) + z16;
            }

    // ---- weight contraction ----
    float lsum = 0.f;
    if (srcA) {
        int la[4]; float sa[4];
        #pragma unroll
        for (int r = 0; r < 4; r++) { la[r] = LABA[rl[r]]; sa[r] = SVA[rl[r]]; }
        if (srcB) {
            int lb[16]; float svb[16];
            #pragma unroll
            for (int j = 0; j < 16; j++) { lb[j] = LABB[cl[j]]; svb[j] = SVB[cl[j]]; }
            #pragma unroll
            for (int r = 0; r < 4; r++) {
                float s = 0.f;
                #pragma unroll
                for (int j = 0; j < 16; j++) {
                    float w = (lb[j] == la[r]) ? svb[j] : 0.f;
                    s = fmaf(w, Kr[r][j], s);
                }
                lsum = fmaf(sa[r], s, lsum);
            }
        } else {
            #pragma unroll
            for (int r = 0; r < 4; r++) {
                const float* wr = &WBT[la[r] * 132];
                float s = 0.f;
                #pragma unroll
                for (int j = 0; j < 16; j++)
                    s = fmaf(wr[cl[j]], Kr[r][j], s);
                lsum = fmaf(sa[r], s, lsum);
            }
        }
    } else {            // tt: both target
        for (int c = 0; c < NCLS; c++) {
            float wbv[16];
            #pragma unroll
            for (int j = 0; j < 16; j++) wbv[j] = WBT[c * 132 + cl[j]];
            #pragma unroll
            for (int r = 0; r < 4; r++) {
                float s = 0.f;
                #pragma unroll
                for (int j = 0; j < 16; j++) s = fmaf(wbv[j], Kr[r][j], s);
                lsum = fmaf(WA[rl[r] * 32 + c], s, lsum);
            }
        }
    }
    if (I != J) lsum *= 2.f;

    // ---- block reduction ----
    __syncthreads();
    RED[tid] = lsum;
    __syncthreads();
    for (int st = 128; st > 0; st >>= 1) {
        if (tid < st) RED[tid] += RED[tid + st];
        __syncthreads();
    }
    if (tid == 0) d_partial[blockIdx.x] = RED[0];
}

__global__ void k_reduce(float* out) {
    __shared__ float red[256];
    int tid = threadIdx.x;
    float s = 0.f;
    for (int i = tid; i < NPAIR; i += 256) s += d_partial[i];
    red[tid] = s;
    __syncthreads();
    for (int st = 128; st > 0; st >>= 1) {
        if (tid < st) red[tid] += red[tid + st];
        __syncthreads();
    }
    if (tid == 0) out[0] = red[0] * d_inv_nidx;
}

extern "C" void kernel_launch(void* const* d_in, const int* in_sizes, int n_in,
                              void* d_out, int out_size) {
    const float* src = (const float*)d_in[0];
    const float* tgt = (const float*)d_in[1];
    const void*  sl  = d_in[2];
    const float* tl  = (const float*)d_in[3];
    float* out = (float*)d_out;

    cudaFuncSetAttribute(k_main, cudaFuncAttributeMaxDynamicSharedMemorySize, SM_TOTAL);

    k_detect  <<<1,    256>>>(sl);
    k_zero    <<<1,    256>>>();
    k_stats   <<<16,   256>>>(sl, tl);
    k_prep    <<<1024, 256>>>(src, tgt);
    k_finalize<<<1,    256>>>();
    k_weights <<<32,   256>>>(sl, tl);
    k_main    <<<NPAIR, 256, SM_TOTAL>>>();
    k_reduce  <<<1,    256>>>(out);
}